// round 4
// baseline (speedup 1.0000x reference)
#include <cuda_runtime.h>
#include <cuda_bf16.h>

#define CI 16
#define CO 16
#define DEG 16
#define BSROW (1 + DEG)            // 17 ints per bs_slice row
#define GROW 48                    // g row: 3*CI floats

#define MAXP 65536
__device__ float g_buf[(size_t)MAXP * GROW];   // scratch: g[p][d*16+i]

// ---------------------------------------------------------------------------
// Kernel A: gather + radial accumulation.  g[p][d*16+i] = sum_j r[p,j,d]*f[nbr_j,i]
// 16 lanes per point: lane=(q,c4); lane loads float4 (ch 4c4..+3) of neighbors
// 4q..4q+3 -> 4 independent LDG.128. Reduce over q by shfl_xor(4), shfl_xor(8).
// ---------------------------------------------------------------------------
#define NITER_A 4
#define PTS_A (16 * NITER_A)       // 64 points per block

__global__ __launch_bounds__(256)
void gather_g_kernel(const float* __restrict__ features,  // [P, CI]
                     const float* __restrict__ radii,     // [P*DEG, 3]
                     const int*   __restrict__ bs,        // [P, 1+DEG]
                     int P)
{
    const int tid  = threadIdx.x;
    const int pt   = tid >> 4;           // group in block (0..15)
    const int t16  = tid & 15;
    const int q    = t16 >> 2;           // neighbor quad
    const int c4   = t16 & 3;            // channel quad
    const int lane = tid & 31;
    const int gbase = lane & ~15;        // group base lane within warp

    const int base = blockIdx.x * PTS_A;

#pragma unroll
    for (int it = 0; it < NITER_A; it++) {
        int p = base + it * 16 + pt;
        const bool valid = (p < P);
        if (p >= P) p = P - 1;           // clamp: keep lanes active for shfl

        // -- indices: 1 coalesced LDG.32 per lane, distribute via 4 shfl --
        const int myv = __ldg(bs + (size_t)p * BSROW + 1 + t16);
        const int idx0 = __shfl_sync(0xffffffffu, myv, gbase + 4 * q + 0);
        const int idx1 = __shfl_sync(0xffffffffu, myv, gbase + 4 * q + 1);
        const int idx2 = __shfl_sync(0xffffffffu, myv, gbase + 4 * q + 2);
        const int idx3 = __shfl_sync(0xffffffffu, myv, gbase + 4 * q + 3);

        // -- radii for this quad: 12 contiguous floats --
        const float4* rp = (const float4*)(radii + ((size_t)p * DEG + 4 * q) * 3);
        float4 rv0 = __ldg(rp + 0);
        float4 rv1 = __ldg(rp + 1);
        float4 rv2 = __ldg(rp + 2);
        float r[12] = { rv0.x, rv0.y, rv0.z, rv0.w, rv1.x, rv1.y,
                        rv1.z, rv1.w, rv2.x, rv2.y, rv2.z, rv2.w };

        // -- 4 independent 16B row gathers --
        const float4* fb = (const float4*)features;
        float4 f0 = __ldg(fb + (size_t)idx0 * (CI / 4) + c4);
        float4 f1 = __ldg(fb + (size_t)idx1 * (CI / 4) + c4);
        float4 f2 = __ldg(fb + (size_t)idx2 * (CI / 4) + c4);
        float4 f3 = __ldg(fb + (size_t)idx3 * (CI / 4) + c4);

        // -- partial g[d][ch]: 48 FMA --
        float g[12];
#pragma unroll
        for (int d = 0; d < 3; d++) {
            g[d * 4 + 0] = r[0 * 3 + d] * f0.x;
            g[d * 4 + 1] = r[0 * 3 + d] * f0.y;
            g[d * 4 + 2] = r[0 * 3 + d] * f0.z;
            g[d * 4 + 3] = r[0 * 3 + d] * f0.w;
            g[d * 4 + 0] = fmaf(r[1 * 3 + d], f1.x, g[d * 4 + 0]);
            g[d * 4 + 1] = fmaf(r[1 * 3 + d], f1.y, g[d * 4 + 1]);
            g[d * 4 + 2] = fmaf(r[1 * 3 + d], f1.z, g[d * 4 + 2]);
            g[d * 4 + 3] = fmaf(r[1 * 3 + d], f1.w, g[d * 4 + 3]);
            g[d * 4 + 0] = fmaf(r[2 * 3 + d], f2.x, g[d * 4 + 0]);
            g[d * 4 + 1] = fmaf(r[2 * 3 + d], f2.y, g[d * 4 + 1]);
            g[d * 4 + 2] = fmaf(r[2 * 3 + d], f2.z, g[d * 4 + 2]);
            g[d * 4 + 3] = fmaf(r[2 * 3 + d], f2.w, g[d * 4 + 3]);
            g[d * 4 + 0] = fmaf(r[3 * 3 + d], f3.x, g[d * 4 + 0]);
            g[d * 4 + 1] = fmaf(r[3 * 3 + d], f3.y, g[d * 4 + 1]);
            g[d * 4 + 2] = fmaf(r[3 * 3 + d], f3.z, g[d * 4 + 2]);
            g[d * 4 + 3] = fmaf(r[3 * 3 + d], f3.w, g[d * 4 + 3]);
        }

        // -- reduce over q --
#pragma unroll
        for (int v = 0; v < 12; v++) g[v] += __shfl_xor_sync(0xffffffffu, g[v], 4);
#pragma unroll
        for (int v = 0; v < 12; v++) g[v] += __shfl_xor_sync(0xffffffffu, g[v], 8);

        // -- lane (q=d, c4) writes g_d[4c4..+3]: STG.128 --
        if (q < 3 && valid) {
            float4 gv = make_float4(g[q * 4 + 0], g[q * 4 + 1],
                                    g[q * 4 + 2], g[q * 4 + 3]);
            *(float4*)(g_buf + (size_t)p * GROW + q * CI + 4 * c4) = gv;
        }
    }
}

// ---------------------------------------------------------------------------
// Kernel B: out[p][o] = sum_k g[p][k] * W[d(k)][o][i(k)],  k = d*16+i.
// Lane = output channel o; W row (48 floats) in registers.
// NITER_B=2 -> 1250 blocks (parallelism); 4 partial accumulators per point
// (chain 192->~60 cyc) so the two unrolled iterations software-pipeline.
// ---------------------------------------------------------------------------
#define NITER_B 2
#define PTS_B (16 * NITER_B)       // 32 points per block

__global__ __launch_bounds__(256)
void contract_w_kernel(const float* __restrict__ W,    // [3, CO, CI]
                       float*       __restrict__ out,  // [P, CO]
                       int P)
{
    const int tid = threadIdx.x;
    const int pt  = tid >> 4;
    const int o   = tid & 15;

    // W[d][o][0..15] for all d: 48 registers
    float wreg[GROW];
#pragma unroll
    for (int d = 0; d < 3; d++) {
        const float4* wrow = (const float4*)(W + (size_t)d * CO * CI + (size_t)o * CI);
#pragma unroll
        for (int qq = 0; qq < 4; qq++) {
            float4 v = __ldg(wrow + qq);
            wreg[d * 16 + qq * 4 + 0] = v.x;
            wreg[d * 16 + qq * 4 + 1] = v.y;
            wreg[d * 16 + qq * 4 + 2] = v.z;
            wreg[d * 16 + qq * 4 + 3] = v.w;
        }
    }

    const int base = blockIdx.x * PTS_B;
#pragma unroll
    for (int it = 0; it < NITER_B; it++) {
        const int p = base + it * 16 + pt;
        if (p >= P) break;

        const float4* gp = (const float4*)(g_buf + (size_t)p * GROW);

        // 12 independent broadcast loads, 4 independent FMA chains
        float4 v[12];
#pragma unroll
        for (int k = 0; k < 12; k++) v[k] = __ldg(gp + k);

        float a0 = 0.f, a1 = 0.f, a2 = 0.f, a3 = 0.f;
#pragma unroll
        for (int k = 0; k < 12; k += 4) {
            a0 = fmaf(wreg[(k+0)*4+0], v[k+0].x, a0);
            a0 = fmaf(wreg[(k+0)*4+1], v[k+0].y, a0);
            a0 = fmaf(wreg[(k+0)*4+2], v[k+0].z, a0);
            a0 = fmaf(wreg[(k+0)*4+3], v[k+0].w, a0);
            a1 = fmaf(wreg[(k+1)*4+0], v[k+1].x, a1);
            a1 = fmaf(wreg[(k+1)*4+1], v[k+1].y, a1);
            a1 = fmaf(wreg[(k+1)*4+2], v[k+1].z, a1);
            a1 = fmaf(wreg[(k+1)*4+3], v[k+1].w, a1);
            a2 = fmaf(wreg[(k+2)*4+0], v[k+2].x, a2);
            a2 = fmaf(wreg[(k+2)*4+1], v[k+2].y, a2);
            a2 = fmaf(wreg[(k+2)*4+2], v[k+2].z, a2);
            a2 = fmaf(wreg[(k+2)*4+3], v[k+2].w, a2);
            a3 = fmaf(wreg[(k+3)*4+0], v[k+3].x, a3);
            a3 = fmaf(wreg[(k+3)*4+1], v[k+3].y, a3);
            a3 = fmaf(wreg[(k+3)*4+2], v[k+3].z, a3);
            a3 = fmaf(wreg[(k+3)*4+3], v[k+3].w, a3);
        }

        out[(size_t)p * CO + o] = (a0 + a1) + (a2 + a3);
    }
}

extern "C" void kernel_launch(void* const* d_in, const int* in_sizes, int n_in,
                              void* d_out, int out_size) {
    const float* features = (const float*)d_in[0];
    const float* radii    = (const float*)d_in[1];
    const float* W        = (const float*)d_in[2];
    const int*   bs       = (const int*)d_in[3];
    float*       out      = (float*)d_out;

    const int P = in_sizes[0] / CI;

    const int blocksA = (P + PTS_A - 1) / PTS_A;   // 625 for P=40000
    gather_g_kernel<<<blocksA, 256>>>(features, radii, bs, P);

    const int blocksB = (P + PTS_B - 1) / PTS_B;   // 1250 for P=40000
    contract_w_kernel<<<blocksB, 256>>>(W, out, P);
}

// round 5
// speedup vs baseline: 1.0204x; 1.0204x over previous
#include <cuda_runtime.h>
#include <cuda_bf16.h>

#define CI 16
#define CO 16
#define DEG 16
#define BSROW (1 + DEG)            // 17 ints per bs_slice row
#define GROW 48                    // g row: 3*CI floats

#define MAXP 65536
__device__ float g_buf[(size_t)MAXP * GROW];   // scratch: g[p][d*16+i]

// ---------------------------------------------------------------------------
// Kernel A: gather + radial accumulation.  g[p][d*16+i] = sum_j r[p,j,d]*f[nbr_j,i]
// 16 lanes per point: lane=(q,c4); lane loads float4 (ch 4c4..+3) of neighbors
// 4q..4q+3 -> 4 independent LDG.128. Reduce over q by shfl_xor(4), shfl_xor(8).
// ---------------------------------------------------------------------------
#define NITER_A 4
#define PTS_A (16 * NITER_A)       // 64 points per block

__global__ __launch_bounds__(256)
void gather_g_kernel(const float* __restrict__ features,  // [P, CI]
                     const float* __restrict__ radii,     // [P*DEG, 3]
                     const int*   __restrict__ bs,        // [P, 1+DEG]
                     int P)
{
    const int tid  = threadIdx.x;
    const int pt   = tid >> 4;           // group in block (0..15)
    const int t16  = tid & 15;
    const int q    = t16 >> 2;           // neighbor quad
    const int c4   = t16 & 3;            // channel quad
    const int lane = tid & 31;
    const int gbase = lane & ~15;        // group base lane within warp

    const int base = blockIdx.x * PTS_A;

#pragma unroll
    for (int it = 0; it < NITER_A; it++) {
        int p = base + it * 16 + pt;
        const bool valid = (p < P);
        if (p >= P) p = P - 1;           // clamp: keep lanes active for shfl

        // -- indices: 1 coalesced LDG.32 per lane, distribute via 4 shfl --
        const int myv = __ldg(bs + (size_t)p * BSROW + 1 + t16);
        const int idx0 = __shfl_sync(0xffffffffu, myv, gbase + 4 * q + 0);
        const int idx1 = __shfl_sync(0xffffffffu, myv, gbase + 4 * q + 1);
        const int idx2 = __shfl_sync(0xffffffffu, myv, gbase + 4 * q + 2);
        const int idx3 = __shfl_sync(0xffffffffu, myv, gbase + 4 * q + 3);

        // -- radii for this quad: 12 contiguous floats --
        const float4* rp = (const float4*)(radii + ((size_t)p * DEG + 4 * q) * 3);
        float4 rv0 = __ldg(rp + 0);
        float4 rv1 = __ldg(rp + 1);
        float4 rv2 = __ldg(rp + 2);
        float r[12] = { rv0.x, rv0.y, rv0.z, rv0.w, rv1.x, rv1.y,
                        rv1.z, rv1.w, rv2.x, rv2.y, rv2.z, rv2.w };

        // -- 4 independent 16B row gathers --
        const float4* fb = (const float4*)features;
        float4 f0 = __ldg(fb + (size_t)idx0 * (CI / 4) + c4);
        float4 f1 = __ldg(fb + (size_t)idx1 * (CI / 4) + c4);
        float4 f2 = __ldg(fb + (size_t)idx2 * (CI / 4) + c4);
        float4 f3 = __ldg(fb + (size_t)idx3 * (CI / 4) + c4);

        // -- partial g[d][ch]: 48 FMA --
        float g[12];
#pragma unroll
        for (int d = 0; d < 3; d++) {
            g[d * 4 + 0] = r[0 * 3 + d] * f0.x;
            g[d * 4 + 1] = r[0 * 3 + d] * f0.y;
            g[d * 4 + 2] = r[0 * 3 + d] * f0.z;
            g[d * 4 + 3] = r[0 * 3 + d] * f0.w;
            g[d * 4 + 0] = fmaf(r[1 * 3 + d], f1.x, g[d * 4 + 0]);
            g[d * 4 + 1] = fmaf(r[1 * 3 + d], f1.y, g[d * 4 + 1]);
            g[d * 4 + 2] = fmaf(r[1 * 3 + d], f1.z, g[d * 4 + 2]);
            g[d * 4 + 3] = fmaf(r[1 * 3 + d], f1.w, g[d * 4 + 3]);
            g[d * 4 + 0] = fmaf(r[2 * 3 + d], f2.x, g[d * 4 + 0]);
            g[d * 4 + 1] = fmaf(r[2 * 3 + d], f2.y, g[d * 4 + 1]);
            g[d * 4 + 2] = fmaf(r[2 * 3 + d], f2.z, g[d * 4 + 2]);
            g[d * 4 + 3] = fmaf(r[2 * 3 + d], f2.w, g[d * 4 + 3]);
            g[d * 4 + 0] = fmaf(r[3 * 3 + d], f3.x, g[d * 4 + 0]);
            g[d * 4 + 1] = fmaf(r[3 * 3 + d], f3.y, g[d * 4 + 1]);
            g[d * 4 + 2] = fmaf(r[3 * 3 + d], f3.z, g[d * 4 + 2]);
            g[d * 4 + 3] = fmaf(r[3 * 3 + d], f3.w, g[d * 4 + 3]);
        }

        // -- reduce over q --
#pragma unroll
        for (int v = 0; v < 12; v++) g[v] += __shfl_xor_sync(0xffffffffu, g[v], 4);
#pragma unroll
        for (int v = 0; v < 12; v++) g[v] += __shfl_xor_sync(0xffffffffu, g[v], 8);

        // -- lane (q=d, c4) writes g_d[4c4..+3]: STG.128 --
        if (q < 3 && valid) {
            float4 gv = make_float4(g[q * 4 + 0], g[q * 4 + 1],
                                    g[q * 4 + 2], g[q * 4 + 3]);
            *(float4*)(g_buf + (size_t)p * GROW + q * CI + 4 * c4) = gv;
        }
    }
}

// ---------------------------------------------------------------------------
// Kernel B: out[p][o] = sum_k g[p][k] * W[d(k)][o][i(k)],  k = d*16+i.
// Stage 32 points' g rows into smem with COALESCED LDG.128 (loads fully
// decoupled from consumers -> full MLP), then compute with W in registers and
// g via 29-cycle LDS.128 broadcast. This removes the load-use chains that
// exposed ~250cyc x 12 per point in the register-resident version.
// ---------------------------------------------------------------------------
#define NPTS_B 32                  // points per block
#define NF4_B (NPTS_B * 12)        // float4s to stage: 384

__global__ __launch_bounds__(256)
void contract_w_kernel(const float* __restrict__ W,    // [3, CO, CI]
                       float*       __restrict__ out,  // [P, CO]
                       int P)
{
    __shared__ float4 s_g4[NF4_B];      // 6 KB: s_g4[pl*12 + k] = g[base+pl][4k..4k+3]

    const int tid = threadIdx.x;
    const int base = blockIdx.x * NPTS_B;
    const int nvalid = min(NPTS_B, P - base);

    // ---- cooperative coalesced stage of g rows ----
    {
        const float4* gsrc = (const float4*)(g_buf + (size_t)base * GROW);
        const int nf4 = nvalid * 12;
        for (int k = tid; k < nf4; k += 256)
            s_g4[k] = __ldg(gsrc + k);
    }

    // ---- W[d][o][0..15] into 48 registers (no competing live array now) ----
    const int pt = tid >> 4;
    const int o  = tid & 15;
    float wreg[GROW];
#pragma unroll
    for (int d = 0; d < 3; d++) {
        const float4* wrow = (const float4*)(W + (size_t)d * CO * CI + (size_t)o * CI);
#pragma unroll
        for (int qq = 0; qq < 4; qq++) {
            float4 v = __ldg(wrow + qq);
            wreg[d * 16 + qq * 4 + 0] = v.x;
            wreg[d * 16 + qq * 4 + 1] = v.y;
            wreg[d * 16 + qq * 4 + 2] = v.z;
            wreg[d * 16 + qq * 4 + 3] = v.w;
        }
    }

    __syncthreads();

    // ---- each 16-lane group handles points pt and pt+16 ----
#pragma unroll
    for (int half = 0; half < 2; half++) {
        const int pl = pt + half * 16;
        if (pl >= nvalid) break;

        const float4* gp = s_g4 + pl * 12;
        float a0 = 0.f, a1 = 0.f, a2 = 0.f, a3 = 0.f;
#pragma unroll
        for (int k = 0; k < 12; k += 4) {
            float4 v0 = gp[k + 0];        // LDS.128 broadcast, 29cyc
            float4 v1 = gp[k + 1];
            float4 v2 = gp[k + 2];
            float4 v3 = gp[k + 3];
            a0 = fmaf(wreg[(k+0)*4+0], v0.x, a0);
            a0 = fmaf(wreg[(k+0)*4+1], v0.y, a0);
            a0 = fmaf(wreg[(k+0)*4+2], v0.z, a0);
            a0 = fmaf(wreg[(k+0)*4+3], v0.w, a0);
            a1 = fmaf(wreg[(k+1)*4+0], v1.x, a1);
            a1 = fmaf(wreg[(k+1)*4+1], v1.y, a1);
            a1 = fmaf(wreg[(k+1)*4+2], v1.z, a1);
            a1 = fmaf(wreg[(k+1)*4+3], v1.w, a1);
            a2 = fmaf(wreg[(k+2)*4+0], v2.x, a2);
            a2 = fmaf(wreg[(k+2)*4+1], v2.y, a2);
            a2 = fmaf(wreg[(k+2)*4+2], v2.z, a2);
            a2 = fmaf(wreg[(k+2)*4+3], v2.w, a2);
            a3 = fmaf(wreg[(k+3)*4+0], v3.x, a3);
            a3 = fmaf(wreg[(k+3)*4+1], v3.y, a3);
            a3 = fmaf(wreg[(k+3)*4+2], v3.z, a3);
            a3 = fmaf(wreg[(k+3)*4+3], v3.w, a3);
        }
        out[(size_t)(base + pl) * CO + o] = (a0 + a1) + (a2 + a3);
    }
}

extern "C" void kernel_launch(void* const* d_in, const int* in_sizes, int n_in,
                              void* d_out, int out_size) {
    const float* features = (const float*)d_in[0];
    const float* radii    = (const float*)d_in[1];
    const float* W        = (const float*)d_in[2];
    const int*   bs       = (const int*)d_in[3];
    float*       out      = (float*)d_out;

    const int P = in_sizes[0] / CI;

    const int blocksA = (P + PTS_A - 1) / PTS_A;   // 625 for P=40000
    gather_g_kernel<<<blocksA, 256>>>(features, radii, bs, P);

    const int blocksB = (P + NPTS_B - 1) / NPTS_B; // 1250 for P=40000
    contract_w_kernel<<<blocksB, 256>>>(W, out, P);
}

// round 6
// speedup vs baseline: 1.3105x; 1.2843x over previous
#include <cuda_runtime.h>
#include <cuda_bf16.h>

#define CI 16
#define CO 16
#define DEG 16
#define BSROW (1 + DEG)            // 17 ints per bs_slice row

#define NITER 4
#define PTS_BLK (16 * NITER)       // 64 points per block

// out[p,o] = sum_j sum_d radii[p*DEG+j,d] * sum_i W[d,o,i] * features[nbr(p,j),i]
// Factored: g_d[i] = sum_j r_jd * f[nbr_j,i];  out[o] = sum_{d,i} W[d,o,i] * g_d[i]
//
// Fully fused, warp-native. 16 lanes per point, lane = (q, c4):
//  Phase 1: lane loads float4 (channels 4c4..+3) of neighbors 4q..4q+3
//           -> 4 independent LDG.128; reduce over q via shfl_xor(4), shfl_xor(8).
//           After reduction EVERY lane holds full g_d[4c4..4c4+3], d=0..2.
//  Phase 2: lane computes part[oo] for o-quad q over its i-quad c4 (48 FMA,
//           W slice W[d][4q+oo][4c4+cc] in 48 regs loaded ONCE per block),
//           reduces over c4 via shfl_xor(1), shfl_xor(2), writes out[p, t16].
// No smem, no barriers, no scratch round-trip, one launch.
__global__ __launch_bounds__(256)
void PeriodicConvolutionPrep_fused(
    const float* __restrict__ features,   // [P, CI]
    const float* __restrict__ radii,      // [P*DEG, 3]
    const float* __restrict__ W,          // [3, CO, CI]
    const int*   __restrict__ bs,         // [P, 1+DEG]
    float*       __restrict__ out,        // [P, CO]
    int P)
{
    const int tid   = threadIdx.x;
    const int t16   = tid & 15;          // lane within point group
    const int q     = t16 >> 2;          // neighbor quad (phase1) / o-quad (phase2)
    const int c4    = t16 & 3;           // channel quad (phase1) / i-quad (phase2)
    const int pt    = tid >> 4;          // point group within block
    const int lane  = tid & 31;
    const int gbase = lane & ~15;        // group base lane within warp

    // ---- W slice for this lane: wreg[d][oo][cc] = W[d][4q+oo][4c4+cc] ----
    // Depends only on t16 -> loaded once, amortized over PTS_BLK points.
    float wreg[3][4][4];
#pragma unroll
    for (int d = 0; d < 3; d++) {
#pragma unroll
        for (int oo = 0; oo < 4; oo++) {
            float4 v = __ldg((const float4*)(W + ((size_t)d * CO + 4 * q + oo) * CI + 4 * c4));
            wreg[d][oo][0] = v.x;
            wreg[d][oo][1] = v.y;
            wreg[d][oo][2] = v.z;
            wreg[d][oo][3] = v.w;
        }
    }

    const int base = blockIdx.x * PTS_BLK;

#pragma unroll
    for (int it = 0; it < NITER; it++) {
        int p = base + it * 16 + pt;
        const bool valid = (p < P);
        if (p >= P) p = P - 1;           // clamp: keep lanes active for shfl

        // -- indices: 1 coalesced LDG.32 per lane, distribute via 4 shfl --
        const int myv  = __ldg(bs + (size_t)p * BSROW + 1 + t16);
        const int idx0 = __shfl_sync(0xffffffffu, myv, gbase + 4 * q + 0);
        const int idx1 = __shfl_sync(0xffffffffu, myv, gbase + 4 * q + 1);
        const int idx2 = __shfl_sync(0xffffffffu, myv, gbase + 4 * q + 2);
        const int idx3 = __shfl_sync(0xffffffffu, myv, gbase + 4 * q + 3);

        // -- radii for this quad: 12 contiguous floats --
        const float4* rp = (const float4*)(radii + ((size_t)p * DEG + 4 * q) * 3);
        float4 rv0 = __ldg(rp + 0);
        float4 rv1 = __ldg(rp + 1);
        float4 rv2 = __ldg(rp + 2);
        float r[12] = { rv0.x, rv0.y, rv0.z, rv0.w, rv1.x, rv1.y,
                        rv1.z, rv1.w, rv2.x, rv2.y, rv2.z, rv2.w };

        // -- 4 independent 16B row gathers --
        const float4* fb = (const float4*)features;
        float4 f0 = __ldg(fb + (size_t)idx0 * (CI / 4) + c4);
        float4 f1 = __ldg(fb + (size_t)idx1 * (CI / 4) + c4);
        float4 f2 = __ldg(fb + (size_t)idx2 * (CI / 4) + c4);
        float4 f3 = __ldg(fb + (size_t)idx3 * (CI / 4) + c4);

        // -- partial g[d][cc] over this lane's 4 neighbors: 48 FMA --
        float g[12];
#pragma unroll
        for (int d = 0; d < 3; d++) {
            g[d * 4 + 0] = r[0 * 3 + d] * f0.x;
            g[d * 4 + 1] = r[0 * 3 + d] * f0.y;
            g[d * 4 + 2] = r[0 * 3 + d] * f0.z;
            g[d * 4 + 3] = r[0 * 3 + d] * f0.w;
            g[d * 4 + 0] = fmaf(r[1 * 3 + d], f1.x, g[d * 4 + 0]);
            g[d * 4 + 1] = fmaf(r[1 * 3 + d], f1.y, g[d * 4 + 1]);
            g[d * 4 + 2] = fmaf(r[1 * 3 + d], f1.z, g[d * 4 + 2]);
            g[d * 4 + 3] = fmaf(r[1 * 3 + d], f1.w, g[d * 4 + 3]);
            g[d * 4 + 0] = fmaf(r[2 * 3 + d], f2.x, g[d * 4 + 0]);
            g[d * 4 + 1] = fmaf(r[2 * 3 + d], f2.y, g[d * 4 + 1]);
            g[d * 4 + 2] = fmaf(r[2 * 3 + d], f2.z, g[d * 4 + 2]);
            g[d * 4 + 3] = fmaf(r[2 * 3 + d], f2.w, g[d * 4 + 3]);
            g[d * 4 + 0] = fmaf(r[3 * 3 + d], f3.x, g[d * 4 + 0]);
            g[d * 4 + 1] = fmaf(r[3 * 3 + d], f3.y, g[d * 4 + 1]);
            g[d * 4 + 2] = fmaf(r[3 * 3 + d], f3.z, g[d * 4 + 2]);
            g[d * 4 + 3] = fmaf(r[3 * 3 + d], f3.w, g[d * 4 + 3]);
        }

        // -- reduce over q: every lane ends with full g_d[4c4..+3] --
#pragma unroll
        for (int v = 0; v < 12; v++) g[v] += __shfl_xor_sync(0xffffffffu, g[v], 4);
#pragma unroll
        for (int v = 0; v < 12; v++) g[v] += __shfl_xor_sync(0xffffffffu, g[v], 8);

        // -- Phase 2: partial out for o-quad q over i-quad c4: 48 FMA --
        float p0 = 0.f, p1 = 0.f, p2 = 0.f, p3 = 0.f;
#pragma unroll
        for (int d = 0; d < 3; d++) {
#pragma unroll
            for (int cc = 0; cc < 4; cc++) {
                const float gv = g[d * 4 + cc];
                p0 = fmaf(wreg[d][0][cc], gv, p0);
                p1 = fmaf(wreg[d][1][cc], gv, p1);
                p2 = fmaf(wreg[d][2][cc], gv, p2);
                p3 = fmaf(wreg[d][3][cc], gv, p3);
            }
        }

        // -- reduce over c4 (lanes xor 1, xor 2 share the same q) --
        p0 += __shfl_xor_sync(0xffffffffu, p0, 1);
        p1 += __shfl_xor_sync(0xffffffffu, p1, 1);
        p2 += __shfl_xor_sync(0xffffffffu, p2, 1);
        p3 += __shfl_xor_sync(0xffffffffu, p3, 1);
        p0 += __shfl_xor_sync(0xffffffffu, p0, 2);
        p1 += __shfl_xor_sync(0xffffffffu, p1, 2);
        p2 += __shfl_xor_sync(0xffffffffu, p2, 2);
        p3 += __shfl_xor_sync(0xffffffffu, p3, 2);

        // -- lane t16 = 4q+c4 writes o = t16: select part[c4], coalesced STG.32 --
        const float res = (c4 == 0) ? p0 : (c4 == 1) ? p1 : (c4 == 2) ? p2 : p3;
        if (valid)
            out[(size_t)p * CO + t16] = res;
    }
}

extern "C" void kernel_launch(void* const* d_in, const int* in_sizes, int n_in,
                              void* d_out, int out_size) {
    const float* features = (const float*)d_in[0];
    const float* radii    = (const float*)d_in[1];
    const float* W        = (const float*)d_in[2];
    const int*   bs       = (const int*)d_in[3];
    float*       out      = (float*)d_out;

    const int P = in_sizes[0] / CI;
    const int blocks = (P + PTS_BLK - 1) / PTS_BLK;   // 625 for P=40000
    PeriodicConvolutionPrep_fused<<<blocks, 256>>>(features, radii, W, bs, out, P);
}

// round 7
// speedup vs baseline: 1.4991x; 1.1439x over previous
#include <cuda_runtime.h>
#include <cuda_bf16.h>

#define CI 16
#define CO 16
#define DEG 16
#define BSROW (1 + DEG)            // 17 ints per bs_slice row

#define NITER 4
#define PTS_BLK (16 * NITER)       // 64 points per block
#define WPAD 52                    // per-lane W slice stride (floats): 208B, bank-conflict-free

// out[p,o] = sum_j sum_d radii[p*DEG+j,d] * sum_i W[d,o,i] * features[nbr(p,j),i]
// Factored: g_d[i] = sum_j r_jd * f[nbr_j,i];  out[o] = sum_{d,i} W[d,o,i] * g_d[i]
//
// Fully fused, warp-native. 16 lanes per point, lane = (q, c4):
//  Phase 1: lane loads float4 (channels 4c4..+3) of neighbors 4q..4q+3
//           -> 4 independent LDG.128; reduce over q via shfl_xor(4), shfl_xor(8).
//  Phase 2: lane computes part[oo] for o-quad q over its i-quad c4 (48 FMA).
//           W slice lives in SMEM (t16-dependent only, loaded once per block)
//           so registers stay ~60 -> 4 CTAs/SM instead of 2.
//           Reduce over c4 via shfl_xor(1), shfl_xor(2); write out[p, t16].
__global__ __launch_bounds__(256)
void PeriodicConvolutionPrep_fused(
    const float* __restrict__ features,   // [P, CI]
    const float* __restrict__ radii,      // [P*DEG, 3]
    const float* __restrict__ W,          // [3, CO, CI]
    const int*   __restrict__ bs,         // [P, 1+DEG]
    float*       __restrict__ out,        // [P, CO]
    int P)
{
    // s_w[t16][d*16 + oo*4 + cc] = W[d][4q+oo][4c4+cc], q=t16>>2, c4=t16&3
    __shared__ float s_w[16][WPAD];       // 3.25 KB

    const int tid   = threadIdx.x;
    const int t16   = tid & 15;          // lane within point group
    const int q     = t16 >> 2;          // neighbor quad (phase1) / o-quad (phase2)
    const int c4    = t16 & 3;           // channel quad (phase1) / i-quad (phase2)
    const int pt    = tid >> 4;          // point group within block
    const int lane  = tid & 31;
    const int gbase = lane & ~15;        // group base lane within warp

    // ---- one-time cooperative W slice staging (threads 0..15, 12 float4 each) ----
    if (tid < 16) {
        const int qq = tid >> 2, cc4 = tid & 3;
#pragma unroll
        for (int d = 0; d < 3; d++) {
#pragma unroll
            for (int oo = 0; oo < 4; oo++) {
                float4 v = __ldg((const float4*)(W + ((size_t)d * CO + 4 * qq + oo) * CI + 4 * cc4));
                *(float4*)&s_w[tid][d * 16 + oo * 4] = v;
            }
        }
    }
    __syncthreads();

    const int base = blockIdx.x * PTS_BLK;

#pragma unroll
    for (int it = 0; it < NITER; it++) {
        int p = base + it * 16 + pt;
        const bool valid = (p < P);
        if (p >= P) p = P - 1;           // clamp: keep lanes active for shfl

        // -- indices: 1 coalesced LDG.32 per lane, distribute via 4 shfl --
        const int myv  = __ldg(bs + (size_t)p * BSROW + 1 + t16);
        const int idx0 = __shfl_sync(0xffffffffu, myv, gbase + 4 * q + 0);
        const int idx1 = __shfl_sync(0xffffffffu, myv, gbase + 4 * q + 1);
        const int idx2 = __shfl_sync(0xffffffffu, myv, gbase + 4 * q + 2);
        const int idx3 = __shfl_sync(0xffffffffu, myv, gbase + 4 * q + 3);

        // -- radii for this quad: 12 contiguous floats --
        const float4* rp = (const float4*)(radii + ((size_t)p * DEG + 4 * q) * 3);
        float4 rv0 = __ldg(rp + 0);
        float4 rv1 = __ldg(rp + 1);
        float4 rv2 = __ldg(rp + 2);
        float r[12] = { rv0.x, rv0.y, rv0.z, rv0.w, rv1.x, rv1.y,
                        rv1.z, rv1.w, rv2.x, rv2.y, rv2.z, rv2.w };

        // -- 4 independent 16B row gathers --
        const float4* fb = (const float4*)features;
        float4 f0 = __ldg(fb + (size_t)idx0 * (CI / 4) + c4);
        float4 f1 = __ldg(fb + (size_t)idx1 * (CI / 4) + c4);
        float4 f2 = __ldg(fb + (size_t)idx2 * (CI / 4) + c4);
        float4 f3 = __ldg(fb + (size_t)idx3 * (CI / 4) + c4);

        // -- partial g[d][cc] over this lane's 4 neighbors: 48 FMA --
        float g[12];
#pragma unroll
        for (int d = 0; d < 3; d++) {
            g[d * 4 + 0] = r[0 * 3 + d] * f0.x;
            g[d * 4 + 1] = r[0 * 3 + d] * f0.y;
            g[d * 4 + 2] = r[0 * 3 + d] * f0.z;
            g[d * 4 + 3] = r[0 * 3 + d] * f0.w;
            g[d * 4 + 0] = fmaf(r[1 * 3 + d], f1.x, g[d * 4 + 0]);
            g[d * 4 + 1] = fmaf(r[1 * 3 + d], f1.y, g[d * 4 + 1]);
            g[d * 4 + 2] = fmaf(r[1 * 3 + d], f1.z, g[d * 4 + 2]);
            g[d * 4 + 3] = fmaf(r[1 * 3 + d], f1.w, g[d * 4 + 3]);
            g[d * 4 + 0] = fmaf(r[2 * 3 + d], f2.x, g[d * 4 + 0]);
            g[d * 4 + 1] = fmaf(r[2 * 3 + d], f2.y, g[d * 4 + 1]);
            g[d * 4 + 2] = fmaf(r[2 * 3 + d], f2.z, g[d * 4 + 2]);
            g[d * 4 + 3] = fmaf(r[2 * 3 + d], f2.w, g[d * 4 + 3]);
            g[d * 4 + 0] = fmaf(r[3 * 3 + d], f3.x, g[d * 4 + 0]);
            g[d * 4 + 1] = fmaf(r[3 * 3 + d], f3.y, g[d * 4 + 1]);
            g[d * 4 + 2] = fmaf(r[3 * 3 + d], f3.z, g[d * 4 + 2]);
            g[d * 4 + 3] = fmaf(r[3 * 3 + d], f3.w, g[d * 4 + 3]);
        }

        // -- reduce over q: every lane ends with full g_d[4c4..+3] --
#pragma unroll
        for (int v = 0; v < 12; v++) g[v] += __shfl_xor_sync(0xffffffffu, g[v], 4);
#pragma unroll
        for (int v = 0; v < 12; v++) g[v] += __shfl_xor_sync(0xffffffffu, g[v], 8);

        // -- Phase 2: partial out for o-quad q over i-quad c4: 12 LDS.128 + 48 FMA --
        float p0 = 0.f, p1 = 0.f, p2 = 0.f, p3 = 0.f;
#pragma unroll
        for (int d = 0; d < 3; d++) {
            float4 w0 = *(const float4*)&s_w[t16][d * 16 + 0];
            float4 w1 = *(const float4*)&s_w[t16][d * 16 + 4];
            float4 w2 = *(const float4*)&s_w[t16][d * 16 + 8];
            float4 w3 = *(const float4*)&s_w[t16][d * 16 + 12];
            const float g0 = g[d * 4 + 0], g1 = g[d * 4 + 1];
            const float g2 = g[d * 4 + 2], g3 = g[d * 4 + 3];
            p0 = fmaf(w0.x, g0, p0); p0 = fmaf(w0.y, g1, p0);
            p0 = fmaf(w0.z, g2, p0); p0 = fmaf(w0.w, g3, p0);
            p1 = fmaf(w1.x, g0, p1); p1 = fmaf(w1.y, g1, p1);
            p1 = fmaf(w1.z, g2, p1); p1 = fmaf(w1.w, g3, p1);
            p2 = fmaf(w2.x, g0, p2); p2 = fmaf(w2.y, g1, p2);
            p2 = fmaf(w2.z, g2, p2); p2 = fmaf(w2.w, g3, p2);
            p3 = fmaf(w3.x, g0, p3); p3 = fmaf(w3.y, g1, p3);
            p3 = fmaf(w3.z, g2, p3); p3 = fmaf(w3.w, g3, p3);
        }

        // -- reduce over c4 (lanes xor 1, xor 2 share the same q) --
        p0 += __shfl_xor_sync(0xffffffffu, p0, 1);
        p1 += __shfl_xor_sync(0xffffffffu, p1, 1);
        p2 += __shfl_xor_sync(0xffffffffu, p2, 1);
        p3 += __shfl_xor_sync(0xffffffffu, p3, 1);
        p0 += __shfl_xor_sync(0xffffffffu, p0, 2);
        p1 += __shfl_xor_sync(0xffffffffu, p1, 2);
        p2 += __shfl_xor_sync(0xffffffffu, p2, 2);
        p3 += __shfl_xor_sync(0xffffffffu, p3, 2);

        // -- lane t16 = 4q+c4 writes o = t16: select part[c4], coalesced STG.32 --
        const float res = (c4 == 0) ? p0 : (c4 == 1) ? p1 : (c4 == 2) ? p2 : p3;
        if (valid)
            out[(size_t)p * CO + t16] = res;
    }
}

extern "C" void kernel_launch(void* const* d_in, const int* in_sizes, int n_in,
                              void* d_out, int out_size) {
    const float* features = (const float*)d_in[0];
    const float* radii    = (const float*)d_in[1];
    const float* W        = (const float*)d_in[2];
    const int*   bs       = (const int*)d_in[3];
    float*       out      = (float*)d_out;

    const int P = in_sizes[0] / CI;
    const int blocks = (P + PTS_BLK - 1) / PTS_BLK;   // 625 for P=40000
    PeriodicConvolutionPrep_fused<<<blocks, 256>>>(features, radii, W, bs, out, P);
}

// round 8
// speedup vs baseline: 1.5634x; 1.0429x over previous
#include <cuda_runtime.h>
#include <cuda_bf16.h>

#define CI 16
#define CO 16
#define DEG 16
#define BSROW (1 + DEG)            // 17 ints per bs_slice row

#define THREADS 128
#define NITER 4
#define PTS_BLK (8 * NITER)        // 8 point-groups * 4 iters = 32 points per block
#define WPAD 52                    // per-lane W slice stride (floats): 208B, conflict-free

// out[p,o] = sum_j sum_d radii[p*DEG+j,d] * sum_i W[d,o,i] * features[nbr(p,j),i]
// Factored: g_d[i] = sum_j r_jd * f[nbr_j,i];  out[o] = sum_{d,i} W[d,o,i] * g_d[i]
//
// Fused, warp-native, SOFTWARE-PIPELINED:
//  - all 4 iterations' neighbor-index words preloaded at entry (kills the
//    idx->shfl->gather serial chain)
//  - features (4x LDG.128) and radii (3x LDG.128, DRAM-streamed) prefetched
//    one iteration ahead in double-buffered registers
//  - phase 1: reduce over neighbor quads via shfl_xor(4), shfl_xor(8)
//  - phase 2: W slice from smem (LDS.128), reduce over c4 via shfl_xor(1),(2)
// 128-thread blocks so ~100 regs still gives 5 CTAs/SM (20 warps).
__global__ __launch_bounds__(THREADS)
void PeriodicConvolutionPrep_fused(
    const float* __restrict__ features,   // [P, CI]
    const float* __restrict__ radii,      // [P*DEG, 3]
    const float* __restrict__ W,          // [3, CO, CI]
    const int*   __restrict__ bs,         // [P, 1+DEG]
    float*       __restrict__ out,        // [P, CO]
    int P)
{
    // s_w[t16][d*16 + oo*4 + cc] = W[d][4q+oo][4c4+cc], q=t16>>2, c4=t16&3
    __shared__ float s_w[16][WPAD];       // 3.25 KB

    const int tid   = threadIdx.x;
    const int t16   = tid & 15;
    const int q     = t16 >> 2;          // neighbor quad (ph1) / o-quad (ph2)
    const int c4    = t16 & 3;           // channel quad (ph1) / i-quad (ph2)
    const int pt    = tid >> 4;          // point group within block (0..7)
    const int lane  = tid & 31;
    const int gbase = lane & ~15;

    if (tid < 16) {
        const int qq = tid >> 2, cc4 = tid & 3;
#pragma unroll
        for (int d = 0; d < 3; d++) {
#pragma unroll
            for (int oo = 0; oo < 4; oo++) {
                float4 v = __ldg((const float4*)(W + ((size_t)d * CO + 4 * qq + oo) * CI + 4 * cc4));
                *(float4*)&s_w[tid][d * 16 + oo * 4] = v;
            }
        }
    }
    __syncthreads();

    const int base = blockIdx.x * PTS_BLK;

    // ---- point ids + validity, clamped ----
    int  p[NITER];
    bool valid[NITER];
#pragma unroll
    for (int it = 0; it < NITER; it++) {
        int pp = base + it * 8 + pt;
        valid[it] = (pp < P);
        p[it] = valid[it] ? pp : (P - 1);
    }

    // ---- preload ALL iterations' index words: 4 independent coalesced LDG.32 ----
    int myv[NITER];
#pragma unroll
    for (int it = 0; it < NITER; it++)
        myv[it] = __ldg(bs + (size_t)p[it] * BSROW + 1 + t16);

    // ---- double-buffered prefetch of features + radii ----
    float4 fpre[2][4];
    float4 rpre[2][3];
    const float4* fb4 = (const float4*)features;

    auto issue_loads = [&](int it, int slot) {
        const int m  = myv[it];
        const int i0 = __shfl_sync(0xffffffffu, m, gbase + 4 * q + 0);
        const int i1 = __shfl_sync(0xffffffffu, m, gbase + 4 * q + 1);
        const int i2 = __shfl_sync(0xffffffffu, m, gbase + 4 * q + 2);
        const int i3 = __shfl_sync(0xffffffffu, m, gbase + 4 * q + 3);
        fpre[slot][0] = __ldg(fb4 + (size_t)i0 * (CI / 4) + c4);
        fpre[slot][1] = __ldg(fb4 + (size_t)i1 * (CI / 4) + c4);
        fpre[slot][2] = __ldg(fb4 + (size_t)i2 * (CI / 4) + c4);
        fpre[slot][3] = __ldg(fb4 + (size_t)i3 * (CI / 4) + c4);
        const float4* rp = (const float4*)(radii + ((size_t)p[it] * DEG + 4 * q) * 3);
        rpre[slot][0] = __ldg(rp + 0);
        rpre[slot][1] = __ldg(rp + 1);
        rpre[slot][2] = __ldg(rp + 2);
    };

    issue_loads(0, 0);

#pragma unroll
    for (int it = 0; it < NITER; it++) {
        const int slot = it & 1;
        if (it + 1 < NITER)
            issue_loads(it + 1, (it + 1) & 1);    // overlap next iter's loads

        const float4 f0 = fpre[slot][0];
        const float4 f1 = fpre[slot][1];
        const float4 f2 = fpre[slot][2];
        const float4 f3 = fpre[slot][3];
        const float4 rv0 = rpre[slot][0];
        const float4 rv1 = rpre[slot][1];
        const float4 rv2 = rpre[slot][2];
        const float r[12] = { rv0.x, rv0.y, rv0.z, rv0.w, rv1.x, rv1.y,
                              rv1.z, rv1.w, rv2.x, rv2.y, rv2.z, rv2.w };

        // -- partial g[d][cc] over this lane's 4 neighbors: 48 FMA --
        float g[12];
#pragma unroll
        for (int d = 0; d < 3; d++) {
            g[d * 4 + 0] = r[0 * 3 + d] * f0.x;
            g[d * 4 + 1] = r[0 * 3 + d] * f0.y;
            g[d * 4 + 2] = r[0 * 3 + d] * f0.z;
            g[d * 4 + 3] = r[0 * 3 + d] * f0.w;
            g[d * 4 + 0] = fmaf(r[1 * 3 + d], f1.x, g[d * 4 + 0]);
            g[d * 4 + 1] = fmaf(r[1 * 3 + d], f1.y, g[d * 4 + 1]);
            g[d * 4 + 2] = fmaf(r[1 * 3 + d], f1.z, g[d * 4 + 2]);
            g[d * 4 + 3] = fmaf(r[1 * 3 + d], f1.w, g[d * 4 + 3]);
            g[d * 4 + 0] = fmaf(r[2 * 3 + d], f2.x, g[d * 4 + 0]);
            g[d * 4 + 1] = fmaf(r[2 * 3 + d], f2.y, g[d * 4 + 1]);
            g[d * 4 + 2] = fmaf(r[2 * 3 + d], f2.z, g[d * 4 + 2]);
            g[d * 4 + 3] = fmaf(r[2 * 3 + d], f2.w, g[d * 4 + 3]);
            g[d * 4 + 0] = fmaf(r[3 * 3 + d], f3.x, g[d * 4 + 0]);
            g[d * 4 + 1] = fmaf(r[3 * 3 + d], f3.y, g[d * 4 + 1]);
            g[d * 4 + 2] = fmaf(r[3 * 3 + d], f3.z, g[d * 4 + 2]);
            g[d * 4 + 3] = fmaf(r[3 * 3 + d], f3.w, g[d * 4 + 3]);
        }

        // -- reduce over q: every lane ends with full g_d[4c4..+3] --
#pragma unroll
        for (int v = 0; v < 12; v++) g[v] += __shfl_xor_sync(0xffffffffu, g[v], 4);
#pragma unroll
        for (int v = 0; v < 12; v++) g[v] += __shfl_xor_sync(0xffffffffu, g[v], 8);

        // -- Phase 2: o-quad q over i-quad c4: 12 LDS.128 + 48 FMA --
        float p0 = 0.f, p1 = 0.f, p2 = 0.f, p3 = 0.f;
#pragma unroll
        for (int d = 0; d < 3; d++) {
            float4 w0 = *(const float4*)&s_w[t16][d * 16 + 0];
            float4 w1 = *(const float4*)&s_w[t16][d * 16 + 4];
            float4 w2 = *(const float4*)&s_w[t16][d * 16 + 8];
            float4 w3 = *(const float4*)&s_w[t16][d * 16 + 12];
            const float g0 = g[d * 4 + 0], g1 = g[d * 4 + 1];
            const float g2 = g[d * 4 + 2], g3 = g[d * 4 + 3];
            p0 = fmaf(w0.x, g0, p0); p0 = fmaf(w0.y, g1, p0);
            p0 = fmaf(w0.z, g2, p0); p0 = fmaf(w0.w, g3, p0);
            p1 = fmaf(w1.x, g0, p1); p1 = fmaf(w1.y, g1, p1);
            p1 = fmaf(w1.z, g2, p1); p1 = fmaf(w1.w, g3, p1);
            p2 = fmaf(w2.x, g0, p2); p2 = fmaf(w2.y, g1, p2);
            p2 = fmaf(w2.z, g2, p2); p2 = fmaf(w2.w, g3, p2);
            p3 = fmaf(w3.x, g0, p3); p3 = fmaf(w3.y, g1, p3);
            p3 = fmaf(w3.z, g2, p3); p3 = fmaf(w3.w, g3, p3);
        }

        // -- reduce over c4 --
        p0 += __shfl_xor_sync(0xffffffffu, p0, 1);
        p1 += __shfl_xor_sync(0xffffffffu, p1, 1);
        p2 += __shfl_xor_sync(0xffffffffu, p2, 1);
        p3 += __shfl_xor_sync(0xffffffffu, p3, 1);
        p0 += __shfl_xor_sync(0xffffffffu, p0, 2);
        p1 += __shfl_xor_sync(0xffffffffu, p1, 2);
        p2 += __shfl_xor_sync(0xffffffffu, p2, 2);
        p3 += __shfl_xor_sync(0xffffffffu, p3, 2);

        const float res = (c4 == 0) ? p0 : (c4 == 1) ? p1 : (c4 == 2) ? p2 : p3;
        if (valid[it])
            out[(size_t)p[it] * CO + t16] = res;
    }
}

extern "C" void kernel_launch(void* const* d_in, const int* in_sizes, int n_in,
                              void* d_out, int out_size) {
    const float* features = (const float*)d_in[0];
    const float* radii    = (const float*)d_in[1];
    const float* W        = (const float*)d_in[2];
    const int*   bs       = (const int*)d_in[3];
    float*       out      = (float*)d_out;

    const int P = in_sizes[0] / CI;
    const int blocks = (P + PTS_BLK - 1) / PTS_BLK;   // 1250 for P=40000
    PeriodicConvolutionPrep_fused<<<blocks, THREADS>>>(features, radii, W, bs, out, P);
}